// round 2
// baseline (speedup 1.0000x reference)
#include <cuda_runtime.h>
#include <cstdint>

#define B_    256
#define NA    196
#define NB    196
#define DK    256
#define DIM   1024
#define SMOOTH 4.0f

// Scratch for attention probabilities: [B, NA, NB] fp32 (allocation-free rule).
__device__ float g_attn[(size_t)B_ * NA * NB];

// ---------------------------------------------------------------------------
// Kernel 1: energy = Q @ K (per batch, [NA,DK]@[DK,NB]), fused softmax over NB.
// Block: 16 a-rows x all 196 columns. 256 threads.
// ---------------------------------------------------------------------------
__global__ __launch_bounds__(256) void energy_softmax_kernel(
    const float* __restrict__ Q,   // [B, NA, DK]
    const float* __restrict__ K)   // [B, DK, NB]
{
    const int b  = blockIdx.y;
    const int a0 = blockIdx.x * 16;

    __shared__ float Qs[16][16];    // [k][a]  (transposed)
    __shared__ float Ks[16][256];   // [k][n]  (padded to 256, zeros beyond 195)
    __shared__ float E[16][208];    // energy tile, padded rows

    const int tid = threadIdx.x;
    const int ty  = tid >> 6;   // 0..3  -> row group (4 rows each)
    const int tx  = tid & 63;   // 0..63 -> column within group of 64

    float acc[4][4];
#pragma unroll
    for (int i = 0; i < 4; i++)
#pragma unroll
        for (int j = 0; j < 4; j++) acc[i][j] = 0.f;

    const float* Qb = Q + (size_t)b * NA * DK;
    const float* Kb = K + (size_t)b * DK * NB;

    const bool j3 = (tx < 4);   // tx+192 < 196 only for tx<4

    for (int k0 = 0; k0 < DK; k0 += 16) {
        // Load Q tile transposed: Qs[k][a], 256 elems / 256 threads
        {
            int a  = tid >> 4;
            int kk = tid & 15;
            float v = 0.f;
            if (a0 + a < NA) v = Qb[(size_t)(a0 + a) * DK + k0 + kk];
            Qs[kk][a] = v;
        }
        // Load K tile: Ks[k][n], zero-fill n >= 196
        for (int idx = tid; idx < 16 * 256; idx += 256) {
            int kk = idx >> 8;
            int n  = idx & 255;
            Ks[kk][n] = (n < NB) ? Kb[(size_t)(k0 + kk) * NB + n] : 0.f;
        }
        __syncthreads();

#pragma unroll
        for (int kk = 0; kk < 16; kk++) {
            float4 qv = *(const float4*)&Qs[kk][ty * 4];
            float kv0 = Ks[kk][tx];
            float kv1 = Ks[kk][tx + 64];
            float kv2 = Ks[kk][tx + 128];
            float kv3 = Ks[kk][tx + 192];  // zero-padded region safe
            acc[0][0] += qv.x * kv0; acc[0][1] += qv.x * kv1; acc[0][2] += qv.x * kv2; acc[0][3] += qv.x * kv3;
            acc[1][0] += qv.y * kv0; acc[1][1] += qv.y * kv1; acc[1][2] += qv.y * kv2; acc[1][3] += qv.y * kv3;
            acc[2][0] += qv.z * kv0; acc[2][1] += qv.z * kv1; acc[2][2] += qv.z * kv2; acc[2][3] += qv.z * kv3;
            acc[3][0] += qv.w * kv0; acc[3][1] += qv.w * kv1; acc[3][2] += qv.w * kv2; acc[3][3] += qv.w * kv3;
        }
        __syncthreads();
    }

    // Write energy * SMOOTH into smem tile
#pragma unroll
    for (int i = 0; i < 4; i++) {
        int r = ty * 4 + i;
        E[r][tx]       = acc[i][0] * SMOOTH;
        E[r][tx + 64]  = acc[i][1] * SMOOTH;
        E[r][tx + 128] = acc[i][2] * SMOOTH;
        if (j3) E[r][tx + 192] = acc[i][3] * SMOOTH;
    }
    __syncthreads();

    // Softmax: 8 warps, 2 rows per warp; 196 cols -> 7 per lane (guarded)
    const int w    = tid >> 5;
    const int lane = tid & 31;
    for (int r = w; r < 16; r += 8) {
        float vals[7];
        float mx = -1e30f;
#pragma unroll
        for (int m = 0; m < 7; m++) {
            int c = lane + 32 * m;
            vals[m] = (c < NB) ? E[r][c] : -1e30f;
            mx = fmaxf(mx, vals[m]);
        }
#pragma unroll
        for (int s = 16; s > 0; s >>= 1)
            mx = fmaxf(mx, __shfl_xor_sync(0xFFFFFFFFu, mx, s));
        float sum = 0.f;
#pragma unroll
        for (int m = 0; m < 7; m++) {
            float e = __expf(vals[m] - mx);
            vals[m] = e;
            sum += e;
        }
#pragma unroll
        for (int s = 16; s > 0; s >>= 1)
            sum += __shfl_xor_sync(0xFFFFFFFFu, sum, s);
        float inv = __frcp_rn(sum);
        int aG = a0 + r;
        if (aG < NA) {
            float* arow = g_attn + ((size_t)b * NA + aG) * NB;
#pragma unroll
            for (int m = 0; m < 7; m++) {
                int c = lane + 32 * m;
                if (c < NB) arow[c] = vals[m] * inv;
            }
        }
    }
}

// ---------------------------------------------------------------------------
// Kernel 2: out[b,d,n] = sum_a VA[b,d,a] * attn[b,a,n] + VB[b,d,n] + gamma
// Per batch GEMM M=1024(d), N=196(n), K=196(a). 64x64x16 tiles, 4x4 per thread.
// ---------------------------------------------------------------------------
__global__ __launch_bounds__(256) void gemm2_kernel(
    const float* __restrict__ VA,     // [B, DIM, NA]
    const float* __restrict__ VB,     // [B, DIM, NB]
    const float* __restrict__ gamma,  // [1]
    float* __restrict__ out)          // [B, DIM, NB]
{
    const int b  = blockIdx.z;
    const int n0 = blockIdx.x * 64;
    const int d0 = blockIdx.y * 64;

    __shared__ float As[16][68];  // [a][d] transposed, padded
    __shared__ float Bs[16][68];  // [a][n], padded

    const int tid = threadIdx.x;
    const int ty  = tid >> 4;   // 0..15 -> d group
    const int tx  = tid & 15;   // 0..15 -> n group

    float acc[4][4];
#pragma unroll
    for (int i = 0; i < 4; i++)
#pragma unroll
        for (int j = 0; j < 4; j++) acc[i][j] = 0.f;

    const float* Ab = VA + (size_t)b * DIM * NA;
    const float* Bb = g_attn + (size_t)b * NA * NB;

    // A-load mapping: row = tid/4 (0..63 d), ac = (tid%4)*4 (a within tile)
    const int arow = tid >> 2;
    const int ac   = (tid & 3) * 4;
    // B-load mapping: a = tid/16 (0..15), nc = (tid%16)*4
    const int ba = tid >> 4;
    const int nc = (tid & 15) * 4;

    for (int k0 = 0; k0 < NA; k0 += 16) {
        // Load A tile (transpose into As[a][d]); 196 % 4 == 0 -> float4 all-or-none
        {
            int aG = k0 + ac;
            float4 v = make_float4(0.f, 0.f, 0.f, 0.f);
            if (aG < NA)  // aG multiple of 4 and NA%4==0 -> aG+3 < NA
                v = *(const float4*)(Ab + (size_t)(d0 + arow) * NA + aG);
            As[ac + 0][arow] = v.x;
            As[ac + 1][arow] = v.y;
            As[ac + 2][arow] = v.z;
            As[ac + 3][arow] = v.w;
        }
        // Load B tile
        {
            int aG = k0 + ba;
            int nG = n0 + nc;
            float4 v = make_float4(0.f, 0.f, 0.f, 0.f);
            if (aG < NA && nG < NB)
                v = *(const float4*)(Bb + (size_t)aG * NB + nG);
            *(float4*)&Bs[ba][nc] = v;
        }
        __syncthreads();

#pragma unroll
        for (int kk = 0; kk < 16; kk++) {
            float4 av = *(const float4*)&As[kk][ty * 4];
            float4 bv = *(const float4*)&Bs[kk][tx * 4];
            acc[0][0] += av.x * bv.x; acc[0][1] += av.x * bv.y; acc[0][2] += av.x * bv.z; acc[0][3] += av.x * bv.w;
            acc[1][0] += av.y * bv.x; acc[1][1] += av.y * bv.y; acc[1][2] += av.y * bv.z; acc[1][3] += av.y * bv.w;
            acc[2][0] += av.z * bv.x; acc[2][1] += av.z * bv.y; acc[2][2] += av.z * bv.z; acc[2][3] += av.z * bv.w;
            acc[3][0] += av.w * bv.x; acc[3][1] += av.w * bv.y; acc[3][2] += av.w * bv.z; acc[3][3] += av.w * bv.w;
        }
        __syncthreads();
    }

    const float g = gamma[0];
    const int n = n0 + tx * 4;
    if (n < NB) {
#pragma unroll
        for (int i = 0; i < 4; i++) {
            int d = d0 + ty * 4 + i;
            const float4 vb = *(const float4*)(VB + ((size_t)b * DIM + d) * NB + n);
            float4 r;
            r.x = acc[i][0] + vb.x + g;
            r.y = acc[i][1] + vb.y + g;
            r.z = acc[i][2] + vb.z + g;
            r.w = acc[i][3] + vb.w + g;
            *(float4*)(out + ((size_t)b * DIM + d) * NB + n) = r;
        }
    }
}

extern "C" void kernel_launch(void* const* d_in, const int* in_sizes, int n_in,
                              void* d_out, int out_size) {
    const float* Q     = (const float*)d_in[0];  // query_a [B, NA, DK]
    const float* VA    = (const float*)d_in[1];  // value_a [B, DIM, NA]
    const float* KB    = (const float*)d_in[2];  // key_b   [B, DK, NB]
    const float* VB    = (const float*)d_in[3];  // value_b [B, DIM, NB]
    const float* gamma = (const float*)d_in[4];  // gamma   [1]
    float* out = (float*)d_out;

    dim3 g1((NA + 15) / 16, B_);          // (13, 256)
    energy_softmax_kernel<<<g1, 256>>>(Q, KB);

    dim3 g2((NB + 63) / 64, DIM / 64, B_); // (4, 16, 256)
    gemm2_kernel<<<g2, 256>>>(VA, VB, gamma, out);
}

// round 6
// speedup vs baseline: 1.6451x; 1.6451x over previous
#include <cuda_runtime.h>
#include <cstdint>

#define B_    256
#define NA    196
#define NB    196
#define DK    256
#define DIM   1024
#define SMOOTH 4.0f

// Scratch: attn TRANSPOSED: [B, NB, NA] fp32
__device__ float g_attn[(size_t)B_ * NB * NA];

__device__ __forceinline__ uint32_t f2tf32(float x) {
    uint32_t u;
    asm("cvt.rna.tf32.f32 %0, %1;" : "=r"(u) : "f"(x));
    return u;
}
__device__ __forceinline__ float4 tf32x4(float4 v) {
    v.x = __uint_as_float(f2tf32(v.x));
    v.y = __uint_as_float(f2tf32(v.y));
    v.z = __uint_as_float(f2tf32(v.z));
    v.w = __uint_as_float(f2tf32(v.w));
    return v;
}
__device__ __forceinline__ void mma_tf32(float* d,
                                         uint32_t a0, uint32_t a1, uint32_t a2, uint32_t a3,
                                         uint32_t b0, uint32_t b1) {
    asm volatile(
        "mma.sync.aligned.m16n8k8.row.col.f32.tf32.tf32.f32 "
        "{%0,%1,%2,%3}, {%4,%5,%6,%7}, {%8,%9}, {%10,%11,%12,%13};\n"
        : "=f"(d[0]), "=f"(d[1]), "=f"(d[2]), "=f"(d[3])
        : "r"(a0), "r"(a1), "r"(a2), "r"(a3), "r"(b0), "r"(b1),
          "f"(d[0]), "f"(d[1]), "f"(d[2]), "f"(d[3]));
}

// ---------------------------------------------------------------------------
// Kernel 1: energy = Q @ K, fused softmax over NB; writes attn TRANSPOSED
// g_attn[b][n][a]. Block: 16 a-rows x full NB. 256 threads.
// ---------------------------------------------------------------------------
__global__ __launch_bounds__(256) void energy_softmax_kernel(
    const float* __restrict__ Q,   // [B, NA, DK]
    const float* __restrict__ K)   // [B, DK, NB]
{
    const int b  = blockIdx.y;
    const int a0 = blockIdx.x * 16;

    __shared__ float Qs[16][16];
    __shared__ float Ks[16][256];
    __shared__ float E[16][208];

    const int tid = threadIdx.x;
    const int ty  = tid >> 6;
    const int tx  = tid & 63;

    float acc[4][4];
#pragma unroll
    for (int i = 0; i < 4; i++)
#pragma unroll
        for (int j = 0; j < 4; j++) acc[i][j] = 0.f;

    const float* Qb = Q + (size_t)b * NA * DK;
    const float* Kb = K + (size_t)b * DK * NB;
    const bool j3 = (tx < 4);

    for (int k0 = 0; k0 < DK; k0 += 16) {
        {
            int a  = tid >> 4;
            int kk = tid & 15;
            float v = 0.f;
            if (a0 + a < NA) v = Qb[(size_t)(a0 + a) * DK + k0 + kk];
            Qs[kk][a] = v;
        }
        for (int idx = tid; idx < 16 * 256; idx += 256) {
            int kk = idx >> 8;
            int n  = idx & 255;
            Ks[kk][n] = (n < NB) ? Kb[(size_t)(k0 + kk) * NB + n] : 0.f;
        }
        __syncthreads();

#pragma unroll
        for (int kk = 0; kk < 16; kk++) {
            float4 qv = *(const float4*)&Qs[kk][ty * 4];
            float kv0 = Ks[kk][tx];
            float kv1 = Ks[kk][tx + 64];
            float kv2 = Ks[kk][tx + 128];
            float kv3 = Ks[kk][tx + 192];
            acc[0][0] += qv.x * kv0; acc[0][1] += qv.x * kv1; acc[0][2] += qv.x * kv2; acc[0][3] += qv.x * kv3;
            acc[1][0] += qv.y * kv0; acc[1][1] += qv.y * kv1; acc[1][2] += qv.y * kv2; acc[1][3] += qv.y * kv3;
            acc[2][0] += qv.z * kv0; acc[2][1] += qv.z * kv1; acc[2][2] += qv.z * kv2; acc[2][3] += qv.z * kv3;
            acc[3][0] += qv.w * kv0; acc[3][1] += qv.w * kv1; acc[3][2] += qv.w * kv2; acc[3][3] += qv.w * kv3;
        }
        __syncthreads();
    }

#pragma unroll
    for (int i = 0; i < 4; i++) {
        int r = ty * 4 + i;
        E[r][tx]       = acc[i][0] * SMOOTH;
        E[r][tx + 64]  = acc[i][1] * SMOOTH;
        E[r][tx + 128] = acc[i][2] * SMOOTH;
        if (j3) E[r][tx + 192] = acc[i][3] * SMOOTH;
    }
    __syncthreads();

    const int w    = tid >> 5;
    const int lane = tid & 31;
    for (int r = w; r < 16; r += 8) {
        float vals[7];
        float mx = -1e30f;
#pragma unroll
        for (int m = 0; m < 7; m++) {
            int c = lane + 32 * m;
            vals[m] = (c < NB) ? E[r][c] : -1e30f;
            mx = fmaxf(mx, vals[m]);
        }
#pragma unroll
        for (int s = 16; s > 0; s >>= 1)
            mx = fmaxf(mx, __shfl_xor_sync(0xFFFFFFFFu, mx, s));
        float sum = 0.f;
#pragma unroll
        for (int m = 0; m < 7; m++) {
            float e = __expf(vals[m] - mx);
            vals[m] = e;
            sum += e;
        }
#pragma unroll
        for (int s = 16; s > 0; s >>= 1)
            sum += __shfl_xor_sync(0xFFFFFFFFu, sum, s);
        float inv = __frcp_rn(sum);
#pragma unroll
        for (int m = 0; m < 7; m++) {
            int c = lane + 32 * m;
            if (c < NB) E[r][c] = vals[m] * inv;
        }
    }
    __syncthreads();

    // Transposed write: thread t = column n; writes up to 16 contiguous a's.
    if (tid < NB) {
        const int navalid = (NA - a0 < 16) ? (NA - a0) : 16;
        float* dst = g_attn + ((size_t)b * NB + tid) * NA + a0;
        for (int j = 0; j < navalid; j += 4) {
            float4 v;
            v.x = E[j + 0][tid];
            v.y = E[j + 1][tid];
            v.z = E[j + 2][tid];
            v.w = E[j + 3][tid];
            *(float4*)(dst + j) = v;
        }
    }
}

// ---------------------------------------------------------------------------
// Kernel 2 (mma.sync tf32): out[b,d,n] = sum_a VA[b,d,a]*attn[a,n] + VB + gamma
// CTA: M=128 (d) x N=104 (n) x K-chunks of 16. 8 warps along M, warp = 16x104.
// A = VA [128,K] row-major (k-contig); B = attnT [104,K] (k-contig) = col-major.
// ---------------------------------------------------------------------------
#define BM 128
#define BN 104
#define BK 16
#define KCH 13            // ceil(196/16)
#define APAD 20           // row stride in floats (16 + 4, keeps 16B alignment)

__global__ __launch_bounds__(256, 2) void gemm2_mma_kernel(
    const float* __restrict__ VA,     // [B, DIM, NA]
    const float* __restrict__ VB,     // [B, DIM, NB]
    const float* __restrict__ gamma,  // [1]
    float* __restrict__ out)          // [B, DIM, NB]
{
    __shared__ float As[2][BM][APAD];   // [d][k] tf32 bits
    __shared__ float Bs[2][BN][APAD];   // [n][k] tf32 bits

    const int tid  = threadIdx.x;
    const int wid  = tid >> 5;
    const int lane = tid & 31;
    const int g    = lane >> 2;     // groupID 0..7
    const int t    = lane & 3;      // thread-in-group 0..3

    const int b  = blockIdx.z;
    const int d0 = blockIdx.y * BM;
    const int n0 = blockIdx.x * BN;

    const float* Abase = VA + ((size_t)b * DIM + d0) * NA;  // [128, NA]
    const float* Bbase = g_attn + ((size_t)b * NB + n0) * NA;

    float c[13][4];
#pragma unroll
    for (int j = 0; j < 13; j++)
#pragma unroll
        for (int i = 0; i < 4; i++) c[j][i] = 0.f;

    // ---- staging index maps ----
    // A: 512 float4 (128 rows x 4), 2 per thread
    const int a_row0 = tid >> 1;            // wrong shape; use idx loop below
    (void)a_row0;

    auto ldg_chunk = [&](int kb, float4 (&ra)[2], float4 (&rb)[2]) {
        const int kbase = kb * BK;
#pragma unroll
        for (int i = 0; i < 2; i++) {
            int idx = i * 256 + tid;              // 0..511
            int row = idx >> 2, c4 = idx & 3;
            int k = kbase + c4 * 4;
            float4 v = make_float4(0.f, 0.f, 0.f, 0.f);
            if (k < NA) v = *(const float4*)(Abase + (size_t)row * NA + k);
            ra[i] = v;
        }
#pragma unroll
        for (int i = 0; i < 2; i++) {
            int idx = i * 256 + tid;              // 0..511, need < 416
            float4 v = make_float4(0.f, 0.f, 0.f, 0.f);
            if (idx < BN * 4) {
                int row = idx >> 2, c4 = idx & 3;
                int k = kbase + c4 * 4;
                if (k < NA && (n0 + row) < NB)
                    v = *(const float4*)(Bbase + (size_t)row * NA + k);
            }
            rb[i] = v;
        }
    };
    auto sts_chunk = [&](int buf, const float4 (&ra)[2], const float4 (&rb)[2]) {
#pragma unroll
        for (int i = 0; i < 2; i++) {
            int idx = i * 256 + tid;
            int row = idx >> 2, c4 = idx & 3;
            *(float4*)&As[buf][row][c4 * 4] = tf32x4(ra[i]);
        }
#pragma unroll
        for (int i = 0; i < 2; i++) {
            int idx = i * 256 + tid;
            if (idx < BN * 4) {
                int row = idx >> 2, c4 = idx & 3;
                *(float4*)&Bs[buf][row][c4 * 4] = tf32x4(rb[i]);
            }
        }
    };

    {
        float4 ra[2], rb[2];
        ldg_chunk(0, ra, rb);
        sts_chunk(0, ra, rb);
    }
    __syncthreads();

    const int wrow = wid * 16;

    for (int kb = 0; kb < KCH; kb++) {
        const int buf = kb & 1;
        float4 ra[2], rb[2];
        if (kb + 1 < KCH) ldg_chunk(kb + 1, ra, rb);

#pragma unroll
        for (int s = 0; s < 2; s++) {
            const int k0 = s * 8;
            uint32_t a0 = __float_as_uint(As[buf][wrow + g][k0 + t]);
            uint32_t a1 = __float_as_uint(As[buf][wrow + g + 8][k0 + t]);
            uint32_t a2 = __float_as_uint(As[buf][wrow + g][k0 + t + 4]);
            uint32_t a3 = __float_as_uint(As[buf][wrow + g + 8][k0 + t + 4]);
#pragma unroll
            for (int j = 0; j < 13; j++) {
                uint32_t b0 = __float_as_uint(Bs[buf][j * 8 + g][k0 + t]);
                uint32_t b1 = __float_as_uint(Bs[buf][j * 8 + g][k0 + t + 4]);
                mma_tf32(c[j], a0, a1, a2, a3, b0, b1);
            }
        }

        if (kb + 1 < KCH) {
            sts_chunk(buf ^ 1, ra, rb);
            __syncthreads();
        }
    }

    // ---- epilogue: direct float2 stores + VB + gamma ----
    const float gam = gamma[0];
    const int row1 = d0 + wrow + g;
    const int row2 = row1 + 8;
#pragma unroll
    for (int j = 0; j < 13; j++) {
        int n = n0 + j * 8 + 2 * t;
        if (n < NB) {   // n even, NB even -> n+1 also valid
            size_t i1 = ((size_t)b * DIM + row1) * NB + n;
            size_t i2 = ((size_t)b * DIM + row2) * NB + n;
            float2 vb1 = *(const float2*)(VB + i1);
            float2 vb2 = *(const float2*)(VB + i2);
            float2 r1 = make_float2(c[j][0] + vb1.x + gam, c[j][1] + vb1.y + gam);
            float2 r2 = make_float2(c[j][2] + vb2.x + gam, c[j][3] + vb2.y + gam);
            *(float2*)(out + i1) = r1;
            *(float2*)(out + i2) = r2;
        }
    }
}

// ---------------------------------------------------------------------------
extern "C" void kernel_launch(void* const* d_in, const int* in_sizes, int n_in,
                              void* d_out, int out_size) {
    const float* Q     = (const float*)d_in[0];  // query_a [B, NA, DK]
    const float* VA    = (const float*)d_in[1];  // value_a [B, DIM, NA]
    const float* KB    = (const float*)d_in[2];  // key_b   [B, DK, NB]
    const float* VB    = (const float*)d_in[3];  // value_b [B, DIM, NB]
    const float* gamma = (const float*)d_in[4];  // gamma   [1]
    float* out = (float*)d_out;

    dim3 g1((NA + 15) / 16, B_);            // (13, 256)
    energy_softmax_kernel<<<g1, 256>>>(Q, KB);

    dim3 g2(2, DIM / BM, B_);               // (2, 8, 256)
    gemm2_mma_kernel<<<g2, 256>>>(VA, VB, gamma, out);
}

// round 9
// speedup vs baseline: 2.0546x; 1.2489x over previous
#include <cuda_runtime.h>
#include <cstdint>

#define B_    256
#define NA    196
#define NB    196
#define DK    256
#define DIM   1024
#define SMOOTH 4.0f

// Scratch: attn TRANSPOSED: [B, NB, NA] fp32
__device__ float g_attn[(size_t)B_ * NB * NA];

__device__ __forceinline__ uint32_t f2tf32(float x) {
    uint32_t u;
    asm("cvt.rna.tf32.f32 %0, %1;" : "=r"(u) : "f"(x));
    return u;
}
__device__ __forceinline__ float tf32f(float x) {
    return __uint_as_float(f2tf32(x));
}
__device__ __forceinline__ float4 tf32x4(float4 v) {
    v.x = tf32f(v.x); v.y = tf32f(v.y); v.z = tf32f(v.z); v.w = tf32f(v.w);
    return v;
}
__device__ __forceinline__ void mma_tf32(float* d,
                                         uint32_t a0, uint32_t a1, uint32_t a2, uint32_t a3,
                                         uint32_t b0, uint32_t b1) {
    asm volatile(
        "mma.sync.aligned.m16n8k8.row.col.f32.tf32.tf32.f32 "
        "{%0,%1,%2,%3}, {%4,%5,%6,%7}, {%8,%9}, {%10,%11,%12,%13};\n"
        : "=f"(d[0]), "=f"(d[1]), "=f"(d[2]), "=f"(d[3])
        : "r"(a0), "r"(a1), "r"(a2), "r"(a3), "r"(b0), "r"(b1),
          "f"(d[0]), "f"(d[1]), "f"(d[2]), "f"(d[3]));
}

// ---------------------------------------------------------------------------
// Kernel 1 (3xTF32 mma.sync): energy = Q @ K (fp32-accurate), fused softmax,
// writes attn TRANSPOSED g_attn[b][n][a].
// CTA: 32 a-rows x 224 n-cols (padded), K=256 in 16 chunks of 16.
// 8 warps: 2 (m) x 4 (n); warp tile 16x56 -> c[7][4].
// Operands split hi/lo; energy = aHi*bHi + aHi*bLo + aLo*bHi.
// ---------------------------------------------------------------------------
#define K1_MT   32
#define K1_NT   224
#define K1_PAD  20
#define K1_EPAD 228
#define K1_CH   16          // DK / 16

// dynamic smem layout (floats):
//   As: [2 buf][2 hl][32][20]   = 2560 floats   (offset 0)
//   Bs: [2 buf][2 hl][224][20]  = 17920 floats  (offset 2560)
//   E:  [32][228]               = 7296 floats   (reuses offset 0)
#define K1_AS_BUF  1280      // floats per A buffer (2 hl planes)
#define K1_AS_HL   640
#define K1_BS_OFF  2560
#define K1_BS_BUF  8960
#define K1_BS_HL   4480
#define K1_SMEM_BYTES 81920

__global__ __launch_bounds__(256) void energy_softmax_mma_kernel(
    const float* __restrict__ Q,   // [B, NA, DK]
    const float* __restrict__ K)   // [B, DK, NB]
{
    extern __shared__ __align__(16) float sm[];
    float* As = sm;                 // hi/lo A planes
    float* Bs = sm + K1_BS_OFF;     // hi/lo B planes
    float* E  = sm;                 // union with staging (safe: used after loop)

    const int tid  = threadIdx.x;
    const int wid  = tid >> 5;
    const int lane = tid & 31;
    const int g    = lane >> 2;
    const int t    = lane & 3;

    const int b  = blockIdx.y;
    const int a0 = blockIdx.x * K1_MT;

    const float* Qb = Q + (size_t)b * NA * DK;
    const float* Kb = K + (size_t)b * DK * NB;

    const int warp_m = (wid >> 2) * 16;      // 0 or 16
    const int warp_n = (wid & 3) * 56;       // 0,56,112,168

    float c[7][4];
#pragma unroll
    for (int j = 0; j < 7; j++)
#pragma unroll
        for (int i = 0; i < 4; i++) c[j][i] = 0.f;

    // A staging: tid<128, one float4: row=tid>>2 (0..31), c4=tid&3
    const int a_row = tid >> 2;
    const int a_c4  = tid & 3;
    const bool a_act = (tid < 128);
    const bool a_val = a_act && (a0 + a_row < NA);
    // B staging: tid<224 owns column n=tid
    const bool b_act = (tid < K1_NT);
    const bool b_val = b_act && (tid < NB);

    float4 av;
    float bv[16];

    auto ldg_chunk = [&](int kb) {
        const int kbase = kb * 16;
        if (a_act) {
            av = make_float4(0.f, 0.f, 0.f, 0.f);
            if (a_val)
                av = *(const float4*)(Qb + (size_t)(a0 + a_row) * DK + kbase + a_c4 * 4);
        }
        if (b_act) {
#pragma unroll
            for (int kk = 0; kk < 16; kk++)
                bv[kk] = b_val ? Kb[(size_t)(kbase + kk) * NB + tid] : 0.f;
        }
    };
    auto sts_chunk = [&](int buf) {
        if (a_act) {
            float4 hi = tf32x4(av);
            float4 lo = make_float4(av.x - hi.x, av.y - hi.y, av.z - hi.z, av.w - hi.w);
            lo = tf32x4(lo);
            float* dstH = As + buf * K1_AS_BUF + a_row * K1_PAD + a_c4 * 4;
            *(float4*)dstH = hi;
            *(float4*)(dstH + K1_AS_HL) = lo;
        }
        if (b_act) {
            float* browH = Bs + buf * K1_BS_BUF + tid * K1_PAD;
#pragma unroll
            for (int g4 = 0; g4 < 4; g4++) {
                float4 v = make_float4(bv[g4 * 4], bv[g4 * 4 + 1], bv[g4 * 4 + 2], bv[g4 * 4 + 3]);
                float4 hi = tf32x4(v);
                float4 lo = make_float4(v.x - hi.x, v.y - hi.y, v.z - hi.z, v.w - hi.w);
                lo = tf32x4(lo);
                *(float4*)(browH + g4 * 4) = hi;
                *(float4*)(browH + K1_BS_HL + g4 * 4) = lo;
            }
        }
    };

    ldg_chunk(0);
    sts_chunk(0);
    __syncthreads();

    for (int kb = 0; kb < K1_CH; kb++) {
        const int buf = kb & 1;
        if (kb + 1 < K1_CH) ldg_chunk(kb + 1);

        const float* AbH = As + buf * K1_AS_BUF;
        const float* AbL = AbH + K1_AS_HL;
        const float* BbH = Bs + buf * K1_BS_BUF;
        const float* BbL = BbH + K1_BS_HL;
#pragma unroll
        for (int s = 0; s < 2; s++) {
            const int k0 = s * 8;
            const int ra1 = (warp_m + g) * K1_PAD + k0 + t;
            const int ra2 = (warp_m + g + 8) * K1_PAD + k0 + t;
            uint32_t ah0 = __float_as_uint(AbH[ra1]);
            uint32_t ah1 = __float_as_uint(AbH[ra2]);
            uint32_t ah2 = __float_as_uint(AbH[ra1 + 4]);
            uint32_t ah3 = __float_as_uint(AbH[ra2 + 4]);
            uint32_t al0 = __float_as_uint(AbL[ra1]);
            uint32_t al1 = __float_as_uint(AbL[ra2]);
            uint32_t al2 = __float_as_uint(AbL[ra1 + 4]);
            uint32_t al3 = __float_as_uint(AbL[ra2 + 4]);
#pragma unroll
            for (int j = 0; j < 7; j++) {
                const int rb = (warp_n + j * 8 + g) * K1_PAD + k0 + t;
                uint32_t bh0 = __float_as_uint(BbH[rb]);
                uint32_t bh1 = __float_as_uint(BbH[rb + 4]);
                uint32_t bl0 = __float_as_uint(BbL[rb]);
                uint32_t bl1 = __float_as_uint(BbL[rb + 4]);
                mma_tf32(c[j], ah0, ah1, ah2, ah3, bl0, bl1);   // hi*lo
                mma_tf32(c[j], al0, al1, al2, al3, bh0, bh1);   // lo*hi
                mma_tf32(c[j], ah0, ah1, ah2, ah3, bh0, bh1);   // hi*hi
            }
        }

        if (kb + 1 < K1_CH) {
            sts_chunk(buf ^ 1);
            __syncthreads();
        }
    }
    __syncthreads();   // staging buffers -> E reuse

    // ---- write energy * SMOOTH into E ----
    {
        const int r1 = warp_m + g;
        const int r2 = r1 + 8;
#pragma unroll
        for (int j = 0; j < 7; j++) {
            const int col = warp_n + j * 8 + 2 * t;
            *(float2*)(E + r1 * K1_EPAD + col) =
                make_float2(c[j][0] * SMOOTH, c[j][1] * SMOOTH);
            *(float2*)(E + r2 * K1_EPAD + col) =
                make_float2(c[j][2] * SMOOTH, c[j][3] * SMOOTH);
        }
    }
    __syncthreads();

    // ---- softmax over n (196 valid cols), 8 warps x 4 rows ----
    for (int r = wid; r < K1_MT; r += 8) {
        float vals[7];
        float mx = -1e30f;
#pragma unroll
        for (int m = 0; m < 7; m++) {
            int cc = lane + 32 * m;
            vals[m] = (cc < NB) ? E[r * K1_EPAD + cc] : -1e30f;
            mx = fmaxf(mx, vals[m]);
        }
#pragma unroll
        for (int s = 16; s > 0; s >>= 1)
            mx = fmaxf(mx, __shfl_xor_sync(0xFFFFFFFFu, mx, s));
        float sum = 0.f;
#pragma unroll
        for (int m = 0; m < 7; m++) {
            float e = __expf(vals[m] - mx);
            vals[m] = e;
            sum += e;
        }
#pragma unroll
        for (int s = 16; s > 0; s >>= 1)
            sum += __shfl_xor_sync(0xFFFFFFFFu, sum, s);
        float inv = __frcp_rn(sum);
#pragma unroll
        for (int m = 0; m < 7; m++) {
            int cc = lane + 32 * m;
            if (cc < NB) E[r * K1_EPAD + cc] = vals[m] * inv;
        }
    }
    __syncthreads();

    // ---- transposed store: thread = column n, contiguous a's ----
    if (tid < NB) {
        const int navalid = (NA - a0 < K1_MT) ? (NA - a0) : K1_MT;
        float* dst = g_attn + ((size_t)b * NB + tid) * NA + a0;
        for (int j = 0; j < navalid; j += 4) {
            float4 v;
            v.x = E[(j + 0) * K1_EPAD + tid];
            v.y = E[(j + 1) * K1_EPAD + tid];
            v.z = E[(j + 2) * K1_EPAD + tid];
            v.w = E[(j + 3) * K1_EPAD + tid];
            *(float4*)(dst + j) = v;
        }
    }
}

// ---------------------------------------------------------------------------
// Kernel 2 (mma.sync tf32): out[b,d,n] = sum_a VA[b,d,a]*attn[a,n] + VB + gamma
// CTA: M=128 (d) x N=104 (n) x K-chunks of 16. 8 warps along M, warp = 16x104.
// ---------------------------------------------------------------------------
#define BM 128
#define BN 104
#define BK 16
#define KCH 13            // ceil(196/16)
#define APAD 20

__global__ __launch_bounds__(256, 2) void gemm2_mma_kernel(
    const float* __restrict__ VA,     // [B, DIM, NA]
    const float* __restrict__ VB,     // [B, DIM, NB]
    const float* __restrict__ gamma,  // [1]
    float* __restrict__ out)          // [B, DIM, NB]
{
    __shared__ float As[2][BM][APAD];   // [d][k] tf32 bits
    __shared__ float Bs[2][BN][APAD];   // [n][k] tf32 bits

    const int tid  = threadIdx.x;
    const int wid  = tid >> 5;
    const int lane = tid & 31;
    const int g    = lane >> 2;
    const int t    = lane & 3;

    const int b  = blockIdx.z;
    const int d0 = blockIdx.y * BM;
    const int n0 = blockIdx.x * BN;

    const float* Abase = VA + ((size_t)b * DIM + d0) * NA;
    const float* Bbase = g_attn + ((size_t)b * NB + n0) * NA;

    float c[13][4];
#pragma unroll
    for (int j = 0; j < 13; j++)
#pragma unroll
        for (int i = 0; i < 4; i++) c[j][i] = 0.f;

    auto ldg_chunk = [&](int kb, float4 (&ra)[2], float4 (&rb)[2]) {
        const int kbase = kb * BK;
#pragma unroll
        for (int i = 0; i < 2; i++) {
            int idx = i * 256 + tid;
            int row = idx >> 2, c4 = idx & 3;
            int k = kbase + c4 * 4;
            float4 v = make_float4(0.f, 0.f, 0.f, 0.f);
            if (k < NA) v = *(const float4*)(Abase + (size_t)row * NA + k);
            ra[i] = v;
        }
#pragma unroll
        for (int i = 0; i < 2; i++) {
            int idx = i * 256 + tid;
            float4 v = make_float4(0.f, 0.f, 0.f, 0.f);
            if (idx < BN * 4) {
                int row = idx >> 2, c4 = idx & 3;
                int k = kbase + c4 * 4;
                if (k < NA && (n0 + row) < NB)
                    v = *(const float4*)(Bbase + (size_t)row * NA + k);
            }
            rb[i] = v;
        }
    };
    auto sts_chunk = [&](int buf, const float4 (&ra)[2], const float4 (&rb)[2]) {
#pragma unroll
        for (int i = 0; i < 2; i++) {
            int idx = i * 256 + tid;
            int row = idx >> 2, c4 = idx & 3;
            *(float4*)&As[buf][row][c4 * 4] = tf32x4(ra[i]);
        }
#pragma unroll
        for (int i = 0; i < 2; i++) {
            int idx = i * 256 + tid;
            if (idx < BN * 4) {
                int row = idx >> 2, c4 = idx & 3;
                *(float4*)&Bs[buf][row][c4 * 4] = tf32x4(rb[i]);
            }
        }
    };

    {
        float4 ra[2], rb[2];
        ldg_chunk(0, ra, rb);
        sts_chunk(0, ra, rb);
    }
    __syncthreads();

    const int wrow = wid * 16;

    for (int kb = 0; kb < KCH; kb++) {
        const int buf = kb & 1;
        float4 ra[2], rb[2];
        if (kb + 1 < KCH) ldg_chunk(kb + 1, ra, rb);

#pragma unroll
        for (int s = 0; s < 2; s++) {
            const int k0 = s * 8;
            uint32_t a0 = __float_as_uint(As[buf][wrow + g][k0 + t]);
            uint32_t a1 = __float_as_uint(As[buf][wrow + g + 8][k0 + t]);
            uint32_t a2 = __float_as_uint(As[buf][wrow + g][k0 + t + 4]);
            uint32_t a3 = __float_as_uint(As[buf][wrow + g + 8][k0 + t + 4]);
#pragma unroll
            for (int j = 0; j < 13; j++) {
                uint32_t b0 = __float_as_uint(Bs[buf][j * 8 + g][k0 + t]);
                uint32_t b1 = __float_as_uint(Bs[buf][j * 8 + g][k0 + t + 4]);
                mma_tf32(c[j], a0, a1, a2, a3, b0, b1);
            }
        }

        if (kb + 1 < KCH) {
            sts_chunk(buf ^ 1, ra, rb);
            __syncthreads();
        }
    }

    const float gam = gamma[0];
    const int row1 = d0 + wrow + g;
    const int row2 = row1 + 8;
#pragma unroll
    for (int j = 0; j < 13; j++) {
        int n = n0 + j * 8 + 2 * t;
        if (n < NB) {
            size_t i1 = ((size_t)b * DIM + row1) * NB + n;
            size_t i2 = ((size_t)b * DIM + row2) * NB + n;
            float2 vb1 = *(const float2*)(VB + i1);
            float2 vb2 = *(const float2*)(VB + i2);
            float2 r1 = make_float2(c[j][0] + vb1.x + gam, c[j][1] + vb1.y + gam);
            float2 r2 = make_float2(c[j][2] + vb2.x + gam, c[j][3] + vb2.y + gam);
            *(float2*)(out + i1) = r1;
            *(float2*)(out + i2) = r2;
        }
    }
}

// ---------------------------------------------------------------------------
extern "C" void kernel_launch(void* const* d_in, const int* in_sizes, int n_in,
                              void* d_out, int out_size) {
    const float* Q     = (const float*)d_in[0];  // query_a [B, NA, DK]
    const float* VA    = (const float*)d_in[1];  // value_a [B, DIM, NA]
    const float* KB    = (const float*)d_in[2];  // key_b   [B, DK, NB]
    const float* VB    = (const float*)d_in[3];  // value_b [B, DIM, NB]
    const float* gamma = (const float*)d_in[4];  // gamma   [1]
    float* out = (float*)d_out;

    cudaFuncSetAttribute(energy_softmax_mma_kernel,
                         cudaFuncAttributeMaxDynamicSharedMemorySize, K1_SMEM_BYTES);

    dim3 g1((NA + K1_MT - 1) / K1_MT, B_);  // (7, 256)
    energy_softmax_mma_kernel<<<g1, 256, K1_SMEM_BYTES>>>(Q, KB);

    dim3 g2(2, DIM / BM, B_);               // (2, 8, 256)
    gemm2_mma_kernel<<<g2, 256>>>(VA, VB, gamma, out);
}

// round 10
// speedup vs baseline: 2.2954x; 1.1172x over previous
#include <cuda_runtime.h>
#include <cstdint>

#define B_    256
#define NA    196
#define NB    196
#define DK    256
#define DIM   1024
#define SMOOTH 4.0f

// Scratch: attn TRANSPOSED: [B, NB, NA] fp32
__device__ float g_attn[(size_t)B_ * NB * NA];

__device__ __forceinline__ uint32_t f2tf32(float x) {
    uint32_t u;
    asm("cvt.rna.tf32.f32 %0, %1;" : "=r"(u) : "f"(x));
    return u;
}
__device__ __forceinline__ float tf32f(float x) {
    return __uint_as_float(f2tf32(x));
}
__device__ __forceinline__ float4 tf32x4(float4 v) {
    v.x = tf32f(v.x); v.y = tf32f(v.y); v.z = tf32f(v.z); v.w = tf32f(v.w);
    return v;
}
__device__ __forceinline__ void mma_tf32(float* d,
                                         uint32_t a0, uint32_t a1, uint32_t a2, uint32_t a3,
                                         uint32_t b0, uint32_t b1) {
    asm volatile(
        "mma.sync.aligned.m16n8k8.row.col.f32.tf32.tf32.f32 "
        "{%0,%1,%2,%3}, {%4,%5,%6,%7}, {%8,%9}, {%10,%11,%12,%13};\n"
        : "=f"(d[0]), "=f"(d[1]), "=f"(d[2]), "=f"(d[3])
        : "r"(a0), "r"(a1), "r"(a2), "r"(a3), "r"(b0), "r"(b1),
          "f"(d[0]), "f"(d[1]), "f"(d[2]), "f"(d[3]));
}
__device__ __forceinline__ uint32_t smem_u32(const void* p) {
    return (uint32_t)__cvta_generic_to_shared(p);
}
__device__ __forceinline__ void cp_async16(uint32_t dst, const void* src, bool pred) {
    int sz = pred ? 16 : 0;
    asm volatile("cp.async.cg.shared.global [%0], [%1], 16, %2;"
                 :: "r"(dst), "l"(src), "r"(sz) : "memory");
}
__device__ __forceinline__ void cp_commit() {
    asm volatile("cp.async.commit_group;" ::: "memory");
}
template <int N>
__device__ __forceinline__ void cp_wait() {
    asm volatile("cp.async.wait_group %0;" :: "n"(N) : "memory");
}

// ---------------------------------------------------------------------------
// Kernel 1 (3xTF32 mma.sync): energy = Q @ K (fp32-accurate), fused softmax,
// writes attn TRANSPOSED g_attn[b][n][a].   (unchanged from R9 — passing)
// ---------------------------------------------------------------------------
#define K1_MT   32
#define K1_NT   224
#define K1_PAD  20
#define K1_EPAD 228
#define K1_CH   16          // DK / 16

#define K1_AS_BUF  1280
#define K1_AS_HL   640
#define K1_BS_OFF  2560
#define K1_BS_BUF  8960
#define K1_BS_HL   4480
#define K1_SMEM_BYTES 81920

__global__ __launch_bounds__(256) void energy_softmax_mma_kernel(
    const float* __restrict__ Q,   // [B, NA, DK]
    const float* __restrict__ K)   // [B, DK, NB]
{
    extern __shared__ __align__(16) float sm[];
    float* As = sm;
    float* Bs = sm + K1_BS_OFF;
    float* E  = sm;

    const int tid  = threadIdx.x;
    const int wid  = tid >> 5;
    const int lane = tid & 31;
    const int g    = lane >> 2;
    const int t    = lane & 3;

    const int b  = blockIdx.y;
    const int a0 = blockIdx.x * K1_MT;

    const float* Qb = Q + (size_t)b * NA * DK;
    const float* Kb = K + (size_t)b * DK * NB;

    const int warp_m = (wid >> 2) * 16;
    const int warp_n = (wid & 3) * 56;

    float c[7][4];
#pragma unroll
    for (int j = 0; j < 7; j++)
#pragma unroll
        for (int i = 0; i < 4; i++) c[j][i] = 0.f;

    const int a_row = tid >> 2;
    const int a_c4  = tid & 3;
    const bool a_act = (tid < 128);
    const bool a_val = a_act && (a0 + a_row < NA);
    const bool b_act = (tid < K1_NT);
    const bool b_val = b_act && (tid < NB);

    float4 av;
    float bv[16];

    auto ldg_chunk = [&](int kb) {
        const int kbase = kb * 16;
        if (a_act) {
            av = make_float4(0.f, 0.f, 0.f, 0.f);
            if (a_val)
                av = *(const float4*)(Qb + (size_t)(a0 + a_row) * DK + kbase + a_c4 * 4);
        }
        if (b_act) {
#pragma unroll
            for (int kk = 0; kk < 16; kk++)
                bv[kk] = b_val ? Kb[(size_t)(kbase + kk) * NB + tid] : 0.f;
        }
    };
    auto sts_chunk = [&](int buf) {
        if (a_act) {
            float4 hi = tf32x4(av);
            float4 lo = make_float4(av.x - hi.x, av.y - hi.y, av.z - hi.z, av.w - hi.w);
            lo = tf32x4(lo);
            float* dstH = As + buf * K1_AS_BUF + a_row * K1_PAD + a_c4 * 4;
            *(float4*)dstH = hi;
            *(float4*)(dstH + K1_AS_HL) = lo;
        }
        if (b_act) {
            float* browH = Bs + buf * K1_BS_BUF + tid * K1_PAD;
#pragma unroll
            for (int g4 = 0; g4 < 4; g4++) {
                float4 v = make_float4(bv[g4 * 4], bv[g4 * 4 + 1], bv[g4 * 4 + 2], bv[g4 * 4 + 3]);
                float4 hi = tf32x4(v);
                float4 lo = make_float4(v.x - hi.x, v.y - hi.y, v.z - hi.z, v.w - hi.w);
                lo = tf32x4(lo);
                *(float4*)(browH + g4 * 4) = hi;
                *(float4*)(browH + K1_BS_HL + g4 * 4) = lo;
            }
        }
    };

    ldg_chunk(0);
    sts_chunk(0);
    __syncthreads();

    for (int kb = 0; kb < K1_CH; kb++) {
        const int buf = kb & 1;
        if (kb + 1 < K1_CH) ldg_chunk(kb + 1);

        const float* AbH = As + buf * K1_AS_BUF;
        const float* AbL = AbH + K1_AS_HL;
        const float* BbH = Bs + buf * K1_BS_BUF;
        const float* BbL = BbH + K1_BS_HL;
#pragma unroll
        for (int s = 0; s < 2; s++) {
            const int k0 = s * 8;
            const int ra1 = (warp_m + g) * K1_PAD + k0 + t;
            const int ra2 = (warp_m + g + 8) * K1_PAD + k0 + t;
            uint32_t ah0 = __float_as_uint(AbH[ra1]);
            uint32_t ah1 = __float_as_uint(AbH[ra2]);
            uint32_t ah2 = __float_as_uint(AbH[ra1 + 4]);
            uint32_t ah3 = __float_as_uint(AbH[ra2 + 4]);
            uint32_t al0 = __float_as_uint(AbL[ra1]);
            uint32_t al1 = __float_as_uint(AbL[ra2]);
            uint32_t al2 = __float_as_uint(AbL[ra1 + 4]);
            uint32_t al3 = __float_as_uint(AbL[ra2 + 4]);
#pragma unroll
            for (int j = 0; j < 7; j++) {
                const int rb = (warp_n + j * 8 + g) * K1_PAD + k0 + t;
                uint32_t bh0 = __float_as_uint(BbH[rb]);
                uint32_t bh1 = __float_as_uint(BbH[rb + 4]);
                uint32_t bl0 = __float_as_uint(BbL[rb]);
                uint32_t bl1 = __float_as_uint(BbL[rb + 4]);
                mma_tf32(c[j], ah0, ah1, ah2, ah3, bl0, bl1);   // hi*lo
                mma_tf32(c[j], al0, al1, al2, al3, bh0, bh1);   // lo*hi
                mma_tf32(c[j], ah0, ah1, ah2, ah3, bh0, bh1);   // hi*hi
            }
        }

        if (kb + 1 < K1_CH) {
            sts_chunk(buf ^ 1);
            __syncthreads();
        }
    }
    __syncthreads();

    {
        const int r1 = warp_m + g;
        const int r2 = r1 + 8;
#pragma unroll
        for (int j = 0; j < 7; j++) {
            const int col = warp_n + j * 8 + 2 * t;
            *(float2*)(E + r1 * K1_EPAD + col) =
                make_float2(c[j][0] * SMOOTH, c[j][1] * SMOOTH);
            *(float2*)(E + r2 * K1_EPAD + col) =
                make_float2(c[j][2] * SMOOTH, c[j][3] * SMOOTH);
        }
    }
    __syncthreads();

    for (int r = wid; r < K1_MT; r += 8) {
        float vals[7];
        float mx = -1e30f;
#pragma unroll
        for (int m = 0; m < 7; m++) {
            int cc = lane + 32 * m;
            vals[m] = (cc < NB) ? E[r * K1_EPAD + cc] : -1e30f;
            mx = fmaxf(mx, vals[m]);
        }
#pragma unroll
        for (int s = 16; s > 0; s >>= 1)
            mx = fmaxf(mx, __shfl_xor_sync(0xFFFFFFFFu, mx, s));
        float sum = 0.f;
#pragma unroll
        for (int m = 0; m < 7; m++) {
            float e = __expf(vals[m] - mx);
            vals[m] = e;
            sum += e;
        }
#pragma unroll
        for (int s = 16; s > 0; s >>= 1)
            sum += __shfl_xor_sync(0xFFFFFFFFu, sum, s);
        float inv = __frcp_rn(sum);
#pragma unroll
        for (int m = 0; m < 7; m++) {
            int cc = lane + 32 * m;
            if (cc < NB) E[r * K1_EPAD + cc] = vals[m] * inv;
        }
    }
    __syncthreads();

    if (tid < NB) {
        const int navalid = (NA - a0 < K1_MT) ? (NA - a0) : K1_MT;
        float* dst = g_attn + ((size_t)b * NB + tid) * NA + a0;
        for (int j = 0; j < navalid; j += 4) {
            float4 v;
            v.x = E[(j + 0) * K1_EPAD + tid];
            v.y = E[(j + 1) * K1_EPAD + tid];
            v.z = E[(j + 2) * K1_EPAD + tid];
            v.w = E[(j + 3) * K1_EPAD + tid];
            *(float4*)(dst + j) = v;
        }
    }
}

// ---------------------------------------------------------------------------
// Kernel 2 (mma.sync tf32, cp.async 4-stage): out = VA @ attn + VB + gamma
// CTA: M=128 x N=104, BK=16 x 13 chunks. Raw fp32 operands (HW tf32 truncate).
// ---------------------------------------------------------------------------
#define BM 128
#define BN 104
#define BK 16
#define KCH 13
#define APAD 20
#define G2_STAGES 4
#define G2_AS   (BM * APAD)         // 2560 floats per A stage
#define G2_BS   (BN * APAD)         // 2080 floats per B stage
#define G2_BOFF (G2_STAGES * G2_AS) // 10240
#define G2_SMEM_BYTES ((G2_STAGES * (G2_AS + G2_BS)) * 4)   // 74240 B

__global__ __launch_bounds__(256, 2) void gemm2_mma_kernel(
    const float* __restrict__ VA,     // [B, DIM, NA]
    const float* __restrict__ VB,     // [B, DIM, NB]
    const float* __restrict__ gamma,  // [1]
    float* __restrict__ out)          // [B, DIM, NB]
{
    extern __shared__ __align__(16) float dsm[];
    float* AsBase = dsm;
    float* BsBase = dsm + G2_BOFF;

    const int tid  = threadIdx.x;
    const int wid  = tid >> 5;
    const int lane = tid & 31;
    const int g    = lane >> 2;
    const int t    = lane & 3;

    const int b  = blockIdx.z;
    const int d0 = blockIdx.y * BM;
    const int n0 = blockIdx.x * BN;

    const float* Abase = VA + ((size_t)b * DIM + d0) * NA;
    const float* Bbase = g_attn + ((size_t)b * NB + n0) * NA;

    float c[13][4];
#pragma unroll
    for (int j = 0; j < 13; j++)
#pragma unroll
        for (int i = 0; i < 4; i++) c[j][i] = 0.f;

    // per-thread cp.async mappings
    const int a_row = tid >> 1;               // A: idx = i*256+tid -> 512 f4
    // computed inside issue to keep regs low

    auto issue_chunk = [&](int kb) {
        const int slot = kb & (G2_STAGES - 1);
        const int kbase = kb * BK;
        float* sa = AsBase + slot * G2_AS;
        float* sb = BsBase + slot * G2_BS;
#pragma unroll
        for (int i = 0; i < 2; i++) {          // A: 512 f4 / 256 thr
            int idx = i * 256 + tid;
            int row = idx >> 2, c4 = idx & 3;
            int k = kbase + c4 * 4;
            bool p = (k < NA);
            const float* src = Abase + (size_t)row * NA + (p ? k : 0);
            cp_async16(smem_u32(sa + row * APAD + c4 * 4), src, p);
        }
#pragma unroll
        for (int i = 0; i < 2; i++) {          // B: 416 f4 / 256 thr
            int idx = i * 256 + tid;
            if (idx < BN * 4) {
                int row = idx >> 2, c4 = idx & 3;
                int k = kbase + c4 * 4;
                bool p = (k < NA) && (n0 + row < NB);
                const float* src = Bbase + (size_t)row * NA + (p ? k : 0);
                cp_async16(smem_u32(sb + row * APAD + c4 * 4), src, p);
            }
        }
        cp_commit();
    };

    // prologue: stages 0..2
    issue_chunk(0);
    issue_chunk(1);
    issue_chunk(2);

    const int wrow = wid * 16;

    for (int kb = 0; kb < KCH; kb++) {
        cp_wait<2>();            // chunk kb's group complete
        __syncthreads();         // also: all threads done computing kb-1 -> slot reusable

        if (kb + 3 < KCH) issue_chunk(kb + 3);
        else cp_commit();        // keep group accounting uniform

        const int slot = kb & (G2_STAGES - 1);
        const float* As = AsBase + slot * G2_AS;
        const float* Bs = BsBase + slot * G2_BS;
#pragma unroll
        for (int s = 0; s < 2; s++) {
            const int k0 = s * 8;
            const int ra1 = (wrow + g) * APAD + k0 + t;
            const int ra2 = (wrow + g + 8) * APAD + k0 + t;
            uint32_t a0 = __float_as_uint(As[ra1]);
            uint32_t a1 = __float_as_uint(As[ra2]);
            uint32_t a2 = __float_as_uint(As[ra1 + 4]);
            uint32_t a3 = __float_as_uint(As[ra2 + 4]);
#pragma unroll
            for (int j = 0; j < 13; j++) {
                const int rb = (j * 8 + g) * APAD + k0 + t;
                uint32_t b0 = __float_as_uint(Bs[rb]);
                uint32_t b1 = __float_as_uint(Bs[rb + 4]);
                mma_tf32(c[j], a0, a1, a2, a3, b0, b1);
            }
        }
    }

    const float gam = gamma[0];
    const int row1 = d0 + wrow + g;
    const int row2 = row1 + 8;
#pragma unroll
    for (int j = 0; j < 13; j++) {
        int n = n0 + j * 8 + 2 * t;
        if (n < NB) {
            size_t i1 = ((size_t)b * DIM + row1) * NB + n;
            size_t i2 = ((size_t)b * DIM + row2) * NB + n;
            float2 vb1 = *(const float2*)(VB + i1);
            float2 vb2 = *(const float2*)(VB + i2);
            float2 r1 = make_float2(c[j][0] + vb1.x + gam, c[j][1] + vb1.y + gam);
            float2 r2 = make_float2(c[j][2] + vb2.x + gam, c[j][3] + vb2.y + gam);
            *(float2*)(out + i1) = r1;
            *(float2*)(out + i2) = r2;
        }
    }
}

// ---------------------------------------------------------------------------
extern "C" void kernel_launch(void* const* d_in, const int* in_sizes, int n_in,
                              void* d_out, int out_size) {
    const float* Q     = (const float*)d_in[0];  // query_a [B, NA, DK]
    const float* VA    = (const float*)d_in[1];  // value_a [B, DIM, NA]
    const float* KB    = (const float*)d_in[2];  // key_b   [B, DK, NB]
    const float* VB    = (const float*)d_in[3];  // value_b [B, DIM, NB]
    const float* gamma = (const float*)d_in[4];  // gamma   [1]
    float* out = (float*)d_out;

    cudaFuncSetAttribute(energy_softmax_mma_kernel,
                         cudaFuncAttributeMaxDynamicSharedMemorySize, K1_SMEM_BYTES);
    cudaFuncSetAttribute(gemm2_mma_kernel,
                         cudaFuncAttributeMaxDynamicSharedMemorySize, G2_SMEM_BYTES);

    dim3 g1((NA + K1_MT - 1) / K1_MT, B_);  // (7, 256)
    energy_softmax_mma_kernel<<<g1, 256, K1_SMEM_BYTES>>>(Q, KB);

    dim3 g2(2, DIM / BM, B_);               // (2, 8, 256)
    gemm2_mma_kernel<<<g2, 256, G2_SMEM_BYTES>>>(VA, VB, gamma, out);
}

// round 12
// speedup vs baseline: 2.4157x; 1.0524x over previous
#include <cuda_runtime.h>
#include <cstdint>

#define B_    256
#define NA    196
#define NB    196
#define DK    256
#define DIM   1024
#define SMOOTH 4.0f

// Scratch: attn TRANSPOSED: [B, NB, NA] fp32
__device__ float g_attn[(size_t)B_ * NB * NA];

__device__ __forceinline__ uint32_t f2tf32(float x) {
    uint32_t u;
    asm("cvt.rna.tf32.f32 %0, %1;" : "=r"(u) : "f"(x));
    return u;
}
__device__ __forceinline__ float tf32f(float x) {
    return __uint_as_float(f2tf32(x));
}
__device__ __forceinline__ float4 tf32x4(float4 v) {
    v.x = tf32f(v.x); v.y = tf32f(v.y); v.z = tf32f(v.z); v.w = tf32f(v.w);
    return v;
}
__device__ __forceinline__ void mma_tf32(float* d,
                                         uint32_t a0, uint32_t a1, uint32_t a2, uint32_t a3,
                                         uint32_t b0, uint32_t b1) {
    asm volatile(
        "mma.sync.aligned.m16n8k8.row.col.f32.tf32.tf32.f32 "
        "{%0,%1,%2,%3}, {%4,%5,%6,%7}, {%8,%9}, {%10,%11,%12,%13};\n"
        : "=f"(d[0]), "=f"(d[1]), "=f"(d[2]), "=f"(d[3])
        : "r"(a0), "r"(a1), "r"(a2), "r"(a3), "r"(b0), "r"(b1),
          "f"(d[0]), "f"(d[1]), "f"(d[2]), "f"(d[3]));
}
__device__ __forceinline__ uint32_t smem_u32(const void* p) {
    return (uint32_t)__cvta_generic_to_shared(p);
}
__device__ __forceinline__ void ldsm_x4(uint32_t& r0, uint32_t& r1,
                                        uint32_t& r2, uint32_t& r3, uint32_t a) {
    asm volatile("ldmatrix.sync.aligned.m8n8.x4.shared.b16 {%0,%1,%2,%3}, [%4];"
                 : "=r"(r0), "=r"(r1), "=r"(r2), "=r"(r3) : "r"(a));
}
__device__ __forceinline__ void ldsm_x2(uint32_t& r0, uint32_t& r1, uint32_t a) {
    asm volatile("ldmatrix.sync.aligned.m8n8.x2.shared.b16 {%0,%1}, [%2];"
                 : "=r"(r0), "=r"(r1) : "r"(a));
}
__device__ __forceinline__ void cp_async16(uint32_t dst, const void* src, bool pred) {
    int sz = pred ? 16 : 0;
    asm volatile("cp.async.cg.shared.global [%0], [%1], 16, %2;"
                 :: "r"(dst), "l"(src), "r"(sz) : "memory");
}
__device__ __forceinline__ void cp_commit() {
    asm volatile("cp.async.commit_group;" ::: "memory");
}
template <int N>
__device__ __forceinline__ void cp_wait() {
    asm volatile("cp.async.wait_group %0;" :: "n"(N) : "memory");
}

// ---------------------------------------------------------------------------
// Kernel 1 (3xTF32 mma.sync + ldmatrix): energy = Q @ K, fused softmax,
// writes attn TRANSPOSED g_attn[b][n][a].
// ---------------------------------------------------------------------------
#define K1_MT   32
#define K1_NT   224
#define K1_PAD  20
#define K1_EPAD 228
#define K1_CH   16          // DK / 16

#define K1_AS_BUF  1280
#define K1_AS_HL   640
#define K1_BS_OFF  2560
#define K1_BS_BUF  8960
#define K1_BS_HL   4480
#define K1_SMEM_BYTES 81920

__global__ __launch_bounds__(256) void energy_softmax_mma_kernel(
    const float* __restrict__ Q,   // [B, NA, DK]
    const float* __restrict__ K)   // [B, DK, NB]
{
    extern __shared__ __align__(16) float sm[];
    float* As = sm;
    float* Bs = sm + K1_BS_OFF;
    float* E  = sm;

    const int tid  = threadIdx.x;
    const int wid  = tid >> 5;
    const int lane = tid & 31;

    const int b  = blockIdx.y;
    const int a0 = blockIdx.x * K1_MT;

    const float* Qb = Q + (size_t)b * NA * DK;
    const float* Kb = K + (size_t)b * DK * NB;

    const int warp_m = (wid >> 2) * 16;
    const int warp_n = (wid & 3) * 56;

    // ldmatrix lane decomposition: m = lane>>3 (matrix), r = lane&7 (row)
    const int lm_hi = (lane >> 3) & 1;   // m & 1
    const int lm_q  = lane >> 4;         // m >> 1
    const int lm_r  = lane & 7;
    const uint32_t smBase = smem_u32(sm);
    // A: row = warp_m + (m&1)*8 + r, byte-in-row = (m>>1)*16
    const uint32_t a_off = (uint32_t)((warp_m + lm_hi * 8 + lm_r) * K1_PAD * 4 + lm_q * 16);
    // B: row = warp_n + j*8 + (m>>1)*8 + r, byte-in-row = (m&1)*16
    const uint32_t b_off = (uint32_t)((warp_n + lm_q * 8 + lm_r) * K1_PAD * 4 + lm_hi * 16);

    float c[7][4];
#pragma unroll
    for (int j = 0; j < 7; j++)
#pragma unroll
        for (int i = 0; i < 4; i++) c[j][i] = 0.f;

    const int a_row = tid >> 2;
    const int a_c4  = tid & 3;
    const bool a_act = (tid < 128);
    const bool a_val = a_act && (a0 + a_row < NA);
    const bool b_act = (tid < K1_NT);
    const bool b_val = b_act && (tid < NB);

    float4 av;
    float bv[16];

    auto ldg_chunk = [&](int kb) {
        const int kbase = kb * 16;
        if (a_act) {
            av = make_float4(0.f, 0.f, 0.f, 0.f);
            if (a_val)
                av = *(const float4*)(Qb + (size_t)(a0 + a_row) * DK + kbase + a_c4 * 4);
        }
        if (b_act) {
#pragma unroll
            for (int kk = 0; kk < 16; kk++)
                bv[kk] = b_val ? Kb[(size_t)(kbase + kk) * NB + tid] : 0.f;
        }
    };
    auto sts_chunk = [&](int buf) {
        if (a_act) {
            float4 hi = tf32x4(av);
            float4 lo = make_float4(av.x - hi.x, av.y - hi.y, av.z - hi.z, av.w - hi.w);
            lo = tf32x4(lo);
            float* dstH = As + buf * K1_AS_BUF + a_row * K1_PAD + a_c4 * 4;
            *(float4*)dstH = hi;
            *(float4*)(dstH + K1_AS_HL) = lo;
        }
        if (b_act) {
            float* browH = Bs + buf * K1_BS_BUF + tid * K1_PAD;
#pragma unroll
            for (int g4 = 0; g4 < 4; g4++) {
                float4 v = make_float4(bv[g4 * 4], bv[g4 * 4 + 1], bv[g4 * 4 + 2], bv[g4 * 4 + 3]);
                float4 hi = tf32x4(v);
                float4 lo = make_float4(v.x - hi.x, v.y - hi.y, v.z - hi.z, v.w - hi.w);
                lo = tf32x4(lo);
                *(float4*)(browH + g4 * 4) = hi;
                *(float4*)(browH + K1_BS_HL + g4 * 4) = lo;
            }
        }
    };

    ldg_chunk(0);
    sts_chunk(0);
    __syncthreads();

    for (int kb = 0; kb < K1_CH; kb++) {
        const int buf = kb & 1;
        if (kb + 1 < K1_CH) ldg_chunk(kb + 1);

        const uint32_t aH = smBase + (buf * K1_AS_BUF) * 4 + a_off;
        const uint32_t aL = aH + K1_AS_HL * 4;
        const uint32_t bH = smBase + (K1_BS_OFF + buf * K1_BS_BUF) * 4 + b_off;
        const uint32_t bL = bH + K1_BS_HL * 4;

#pragma unroll
        for (int s = 0; s < 2; s++) {
            uint32_t ah0, ah1, ah2, ah3, al0, al1, al2, al3;
            ldsm_x4(ah0, ah1, ah2, ah3, aH + s * 32);
            ldsm_x4(al0, al1, al2, al3, aL + s * 32);
#pragma unroll
            for (int jp = 0; jp < 3; jp++) {
                uint32_t bh0, bh1, bh2, bh3, bl0, bl1, bl2, bl3;
                ldsm_x4(bh0, bh1, bh2, bh3, bH + jp * 1280 + s * 32);
                ldsm_x4(bl0, bl1, bl2, bl3, bL + jp * 1280 + s * 32);
                mma_tf32(c[2 * jp],     ah0, ah1, ah2, ah3, bl0, bl1);
                mma_tf32(c[2 * jp],     al0, al1, al2, al3, bh0, bh1);
                mma_tf32(c[2 * jp],     ah0, ah1, ah2, ah3, bh0, bh1);
                mma_tf32(c[2 * jp + 1], ah0, ah1, ah2, ah3, bl2, bl3);
                mma_tf32(c[2 * jp + 1], al0, al1, al2, al3, bh2, bh3);
                mma_tf32(c[2 * jp + 1], ah0, ah1, ah2, ah3, bh2, bh3);
            }
            {
                uint32_t bh0, bh1, bl0, bl1;
                ldsm_x2(bh0, bh1, bH + 6 * 640 + s * 32);
                ldsm_x2(bl0, bl1, bL + 6 * 640 + s * 32);
                mma_tf32(c[6], ah0, ah1, ah2, ah3, bl0, bl1);
                mma_tf32(c[6], al0, al1, al2, al3, bh0, bh1);
                mma_tf32(c[6], ah0, ah1, ah2, ah3, bh0, bh1);
            }
        }

        if (kb + 1 < K1_CH) {
            sts_chunk(buf ^ 1);
            __syncthreads();
        }
    }
    __syncthreads();

    // ---- write energy * SMOOTH into E ----
    {
        const int g = lane >> 2;
        const int t = lane & 3;
        const int r1 = warp_m + g;
        const int r2 = r1 + 8;
#pragma unroll
        for (int j = 0; j < 7; j++) {
            const int col = warp_n + j * 8 + 2 * t;
            *(float2*)(E + r1 * K1_EPAD + col) =
                make_float2(c[j][0] * SMOOTH, c[j][1] * SMOOTH);
            *(float2*)(E + r2 * K1_EPAD + col) =
                make_float2(c[j][2] * SMOOTH, c[j][3] * SMOOTH);
        }
    }
    __syncthreads();

    for (int r = wid; r < K1_MT; r += 8) {
        float vals[7];
        float mx = -1e30f;
#pragma unroll
        for (int m = 0; m < 7; m++) {
            int cc = lane + 32 * m;
            vals[m] = (cc < NB) ? E[r * K1_EPAD + cc] : -1e30f;
            mx = fmaxf(mx, vals[m]);
        }
#pragma unroll
        for (int s = 16; s > 0; s >>= 1)
            mx = fmaxf(mx, __shfl_xor_sync(0xFFFFFFFFu, mx, s));
        float sum = 0.f;
#pragma unroll
        for (int m = 0; m < 7; m++) {
            float e = __expf(vals[m] - mx);
            vals[m] = e;
            sum += e;
        }
#pragma unroll
        for (int s = 16; s > 0; s >>= 1)
            sum += __shfl_xor_sync(0xFFFFFFFFu, sum, s);
        float inv = __frcp_rn(sum);
#pragma unroll
        for (int m = 0; m < 7; m++) {
            int cc = lane + 32 * m;
            if (cc < NB) E[r * K1_EPAD + cc] = vals[m] * inv;
        }
    }
    __syncthreads();

    if (tid < NB) {
        const int navalid = (NA - a0 < K1_MT) ? (NA - a0) : K1_MT;
        float* dst = g_attn + ((size_t)b * NB + tid) * NA + a0;
        for (int j = 0; j < navalid; j += 4) {
            float4 v;
            v.x = E[(j + 0) * K1_EPAD + tid];
            v.y = E[(j + 1) * K1_EPAD + tid];
            v.z = E[(j + 2) * K1_EPAD + tid];
            v.w = E[(j + 3) * K1_EPAD + tid];
            *(float4*)(dst + j) = v;
        }
    }
}

// ---------------------------------------------------------------------------
// Kernel 2 (mma.sync tf32, cp.async 4-stage + ldmatrix)
// ---------------------------------------------------------------------------
#define BM 128
#define BN 104
#define BK 16
#define KCH 13
#define APAD 20
#define G2_STAGES 4
#define G2_AS   (BM * APAD)
#define G2_BS   (BN * APAD)
#define G2_BOFF (G2_STAGES * G2_AS)
#define G2_SMEM_BYTES ((G2_STAGES * (G2_AS + G2_BS)) * 4)   // 74240 B

__global__ __launch_bounds__(256, 2) void gemm2_mma_kernel(
    const float* __restrict__ VA,     // [B, DIM, NA]
    const float* __restrict__ VB,     // [B, DIM, NB]
    const float* __restrict__ gamma,  // [1]
    float* __restrict__ out)          // [B, DIM, NB]
{
    extern __shared__ __align__(16) float dsm[];
    float* AsBase = dsm;
    float* BsBase = dsm + G2_BOFF;

    const int tid  = threadIdx.x;
    const int wid  = tid >> 5;
    const int lane = tid & 31;

    const int b  = blockIdx.z;
    const int d0 = blockIdx.y * BM;
    const int n0 = blockIdx.x * BN;

    const float* Abase = VA + ((size_t)b * DIM + d0) * NA;
    const float* Bbase = g_attn + ((size_t)b * NB + n0) * NA;

    const int wrow = wid * 16;
    const int lm_hi = (lane >> 3) & 1;
    const int lm_q  = lane >> 4;
    const int lm_r  = lane & 7;
    const uint32_t smBase = smem_u32(dsm);
    const uint32_t a_off = (uint32_t)((wrow + lm_hi * 8 + lm_r) * APAD * 4 + lm_q * 16);
    const uint32_t b_off = (uint32_t)((lm_q * 8 + lm_r) * APAD * 4 + lm_hi * 16);

    float c[13][4];
#pragma unroll
    for (int j = 0; j < 13; j++)
#pragma unroll
        for (int i = 0; i < 4; i++) c[j][i] = 0.f;

    auto issue_chunk = [&](int kb) {
        const int slot = kb & (G2_STAGES - 1);
        const int kbase = kb * BK;
        float* sa = AsBase + slot * G2_AS;
        float* sb = BsBase + slot * G2_BS;
#pragma unroll
        for (int i = 0; i < 2; i++) {
            int idx = i * 256 + tid;
            int row = idx >> 2, c4 = idx & 3;
            int k = kbase + c4 * 4;
            bool p = (k < NA);
            const float* src = Abase + (size_t)row * NA + (p ? k : 0);
            cp_async16(smem_u32(sa + row * APAD + c4 * 4), src, p);
        }
#pragma unroll
        for (int i = 0; i < 2; i++) {
            int idx = i * 256 + tid;
            if (idx < BN * 4) {
                int row = idx >> 2, c4 = idx & 3;
                int k = kbase + c4 * 4;
                bool p = (k < NA) && (n0 + row < NB);
                const float* src = Bbase + (size_t)row * NA + (p ? k : 0);
                cp_async16(smem_u32(sb + row * APAD + c4 * 4), src, p);
            }
        }
        cp_commit();
    };

    issue_chunk(0);
    issue_chunk(1);
    issue_chunk(2);

    for (int kb = 0; kb < KCH; kb++) {
        cp_wait<2>();
        __syncthreads();

        if (kb + 3 < KCH) issue_chunk(kb + 3);
        else cp_commit();

        const int slot = kb & (G2_STAGES - 1);
        const uint32_t aA = smBase + (slot * G2_AS) * 4 + a_off;
        const uint32_t bA = smBase + (G2_BOFF + slot * G2_BS) * 4 + b_off;

#pragma unroll
        for (int s = 0; s < 2; s++) {
            uint32_t a0, a1, a2, a3;
            ldsm_x4(a0, a1, a2, a3, aA + s * 32);
#pragma unroll
            for (int jp = 0; jp < 6; jp++) {
                uint32_t b0, b1, b2, b3;
                ldsm_x4(b0, b1, b2, b3, bA + jp * 1280 + s * 32);
                mma_tf32(c[2 * jp],     a0, a1, a2, a3, b0, b1);
                mma_tf32(c[2 * jp + 1], a0, a1, a2, a3, b2, b3);
            }
            {
                uint32_t b0, b1;
                ldsm_x2(b0, b1, bA + 12 * 640 + s * 32);
                mma_tf32(c[12], a0, a1, a2, a3, b0, b1);
            }
        }
    }

    const float gam = gamma[0];
    const int g = lane >> 2;
    const int t = lane & 3;
    const int row1 = d0 + wrow + g;
    const int row2 = row1 + 8;
#pragma unroll
    for (int j = 0; j < 13; j++) {
        int n = n0 + j * 8 + 2 * t;
        if (n < NB) {
            size_t i1 = ((size_t)b * DIM + row1) * NB + n;
            size_t i2 = ((size_t)b * DIM + row2) * NB + n;
            float2 vb1 = *(const float2*)(VB + i1);
            float2 vb2 = *(const float2*)(VB + i2);
            float2 r1 = make_float2(c[j][0] + vb1.x + gam, c[j][1] + vb1.y + gam);
            float2 r2 = make_float2(c[j][2] + vb2.x + gam, c[j][3] + vb2.y + gam);
            *(float2*)(out + i1) = r1;
            *(float2*)(out + i2) = r2;
        }
    }
}

// ---------------------------------------------------------------------------
extern "C" void kernel_launch(void* const* d_in, const int* in_sizes, int n_in,
                              void* d_out, int out_size) {
    const float* Q     = (const float*)d_in[0];  // query_a [B, NA, DK]
    const float* VA    = (const float*)d_in[1];  // value_a [B, DIM, NA]
    const float* KB    = (const float*)d_in[2];  // key_b   [B, DK, NB]
    const float* VB    = (const float*)d_in[3];  // value_b [B, DIM, NB]
    const float* gamma = (const float*)d_in[4];  // gamma   [1]
    float* out = (float*)d_out;

    cudaFuncSetAttribute(energy_softmax_mma_kernel,
                         cudaFuncAttributeMaxDynamicSharedMemorySize, K1_SMEM_BYTES);
    cudaFuncSetAttribute(gemm2_mma_kernel,
                         cudaFuncAttributeMaxDynamicSharedMemorySize, G2_SMEM_BYTES);

    dim3 g1((NA + K1_MT - 1) / K1_MT, B_);  // (7, 256)
    energy_softmax_mma_kernel<<<g1, 256, K1_SMEM_BYTES>>>(Q, KB);

    dim3 g2(2, DIM / BM, B_);               // (2, 8, 256)
    gemm2_mma_kernel<<<g2, 256, G2_SMEM_BYTES>>>(VA, VB, gamma, out);
}